// round 5
// baseline (speedup 1.0000x reference)
#include <cuda_runtime.h>
#include <math.h>

// Problem constants
#define BT   2048      // B*T
#define DIM  2048      // D
#define NH   4         // H
#define TOPK 8         // K
#define DK   64
#define NKEY 128       // NK
#define QC   512       // 2*H*DK

// Scratch (device globals — no allocation allowed)
__device__ float g_q[BT * QC];            // 4 MB
__device__ float g_scores[BT * NH * TOPK];
__device__ int   g_indices[BT * NH * TOPK];

// ---------------------------------------------------------------------------
// K1: q = x @ Wq   (M=2048, N=512, K=2048) fp32 SGEMM, 64x64 tile, 4x4/thread.
// Accuracy-hardened: per-16-k-tile partial sums (2 interleaved chains) +
// Kahan compensated combine across tiles. Keeps q within ~1e-7 of correctly
// rounded so routing top-k matches the reference's selection.
// ---------------------------------------------------------------------------
__global__ __launch_bounds__(256) void qproj_kernel(const float* __restrict__ A,
                                                    const float* __restrict__ Bm) {
    __shared__ __align__(16) float As[16][68];   // k-major (transposed)
    __shared__ __align__(16) float Bs[16][68];

    const int t  = threadIdx.x;
    const int m0 = blockIdx.y * 64;
    const int n0 = blockIdx.x * 64;
    const int cx = t & 15;         // col group
    const int cy = t >> 4;         // row group
    const int ar = t >> 2, ac = t & 3;     // A-load mapping (64 rows x 4 float4)
    const int br = t >> 4, bc = t & 15;    // B-load mapping (16 rows x 16 float4)

    float acc[4][4];   // Kahan sum
    float cmp[4][4];   // Kahan compensation
    #pragma unroll
    for (int i = 0; i < 4; i++)
        #pragma unroll
        for (int j = 0; j < 4; j++) { acc[i][j] = 0.f; cmp[i][j] = 0.f; }

    for (int k0 = 0; k0 < DIM; k0 += 16) {
        float4 va = *(const float4*)(A  + (size_t)(m0 + ar) * DIM + k0 + ac * 4);
        float4 vb = *(const float4*)(Bm + (size_t)(k0 + br) * QC  + n0 + bc * 4);
        As[ac * 4 + 0][ar] = va.x;
        As[ac * 4 + 1][ar] = va.y;
        As[ac * 4 + 2][ar] = va.z;
        As[ac * 4 + 3][ar] = va.w;
        *(float4*)(&Bs[br][bc * 4]) = vb;
        __syncthreads();

        // two interleaved partial chains within the tile (even/odd kk)
        float ta[4][4], tb[4][4];
        #pragma unroll
        for (int i = 0; i < 4; i++)
            #pragma unroll
            for (int j = 0; j < 4; j++) { ta[i][j] = 0.f; tb[i][j] = 0.f; }

        #pragma unroll
        for (int kk = 0; kk < 16; kk += 2) {
            float4 a0 = *(const float4*)(&As[kk][cy * 4]);
            float4 b0 = *(const float4*)(&Bs[kk][cx * 4]);
            float4 a1 = *(const float4*)(&As[kk + 1][cy * 4]);
            float4 b1 = *(const float4*)(&Bs[kk + 1][cx * 4]);
            float av0[4] = {a0.x, a0.y, a0.z, a0.w};
            float bv0[4] = {b0.x, b0.y, b0.z, b0.w};
            float av1[4] = {a1.x, a1.y, a1.z, a1.w};
            float bv1[4] = {b1.x, b1.y, b1.z, b1.w};
            #pragma unroll
            for (int i = 0; i < 4; i++)
                #pragma unroll
                for (int j = 0; j < 4; j++) {
                    ta[i][j] = fmaf(av0[i], bv0[j], ta[i][j]);
                    tb[i][j] = fmaf(av1[i], bv1[j], tb[i][j]);
                }
        }
        __syncthreads();

        // Kahan-combine tile sum into running accumulator.
        // __fadd_rn/__fsub_rn are never reassociated/contracted by the compiler.
        #pragma unroll
        for (int i = 0; i < 4; i++)
            #pragma unroll
            for (int j = 0; j < 4; j++) {
                float ts = __fadd_rn(ta[i][j], tb[i][j]);
                float y  = __fsub_rn(ts, cmp[i][j]);
                float t2 = __fadd_rn(acc[i][j], y);
                cmp[i][j] = __fsub_rn(__fsub_rn(t2, acc[i][j]), y);
                acc[i][j] = t2;
            }
    }

    #pragma unroll
    for (int i = 0; i < 4; i++) {
        float4 o = make_float4(acc[i][0], acc[i][1], acc[i][2], acc[i][3]);
        *(float4*)(&g_q[(size_t)(m0 + cy * 4 + i) * QC + n0 + cx * 4]) = o;
    }
}

// ---------------------------------------------------------------------------
// K2: per (token, head): sims vs 128 keys (both halves), top-8 each,
//     64 pairwise sums, top-8 of those -> final scores + flat indices.
// 1 block of 128 threads per (bt, h). Tie-break = lowest index (matches jax).
// ---------------------------------------------------------------------------
__global__ __launch_bounds__(128) void route_kernel(const float* __restrict__ keys) {
    const int bid = blockIdx.x;
    const int bt  = bid >> 2;       // / NH
    const int h   = bid & 3;        // % NH
    const int t   = threadIdx.x;

    __shared__ __align__(16) float qs[128];   // q1[0:64], q2[64:128]
    __shared__ float wv[128];
    __shared__ float redv[128];
    __shared__ int   redi[128];
    __shared__ float s1sel[TOPK], s2sel[TOPK];
    __shared__ int   i1sel[TOPK], i2sel[TOPK];
    __shared__ float pv[64];
    __shared__ int   pidx[64];

    qs[t] = g_q[(size_t)bt * QC + h * 128 + t];
    __syncthreads();

    // sims: thread t handles key index t for both halves (4 partial chains each)
    float s1, s2;
    {
        const float4* q1 = (const float4*)(qs);
        const float4* q2 = (const float4*)(qs + 64);
        const float4* k1 = (const float4*)(keys + (size_t)((h * NKEY + t) * 2 + 0) * DK);
        const float4* k2 = (const float4*)(keys + (size_t)((h * NKEY + t) * 2 + 1) * DK);
        float p1[4] = {0.f, 0.f, 0.f, 0.f};
        float p2[4] = {0.f, 0.f, 0.f, 0.f};
        #pragma unroll
        for (int i = 0; i < 16; i += 4) {
            #pragma unroll
            for (int u = 0; u < 4; u++) {
                float4 a = q1[i + u], b = k1[i + u];
                p1[u] = fmaf(a.x, b.x, fmaf(a.y, b.y, fmaf(a.z, b.z, fmaf(a.w, b.w, p1[u]))));
                float4 c = q2[i + u], d = k2[i + u];
                p2[u] = fmaf(c.x, d.x, fmaf(c.y, d.y, fmaf(c.z, d.z, fmaf(c.w, d.w, p2[u]))));
            }
        }
        s1 = __fadd_rn(__fadd_rn(p1[0], p1[1]), __fadd_rn(p1[2], p1[3]));
        s2 = __fadd_rn(__fadd_rn(p2[0], p2[1]), __fadd_rn(p2[2], p2[3]));
    }

    // top-8 of s1
    wv[t] = s1;
    __syncthreads();
    for (int r = 0; r < TOPK; r++) {
        redv[t] = wv[t]; redi[t] = t;
        __syncthreads();
        #pragma unroll
        for (int s = 64; s > 0; s >>= 1) {
            if (t < s) {
                float ov = redv[t + s]; int oi = redi[t + s];
                if (ov > redv[t] || (ov == redv[t] && oi < redi[t])) { redv[t] = ov; redi[t] = oi; }
            }
            __syncthreads();
        }
        if (t == 0) { s1sel[r] = redv[0]; i1sel[r] = redi[0]; wv[redi[0]] = -1e30f; }
        __syncthreads();
    }

    // top-8 of s2
    wv[t] = s2;
    __syncthreads();
    for (int r = 0; r < TOPK; r++) {
        redv[t] = wv[t]; redi[t] = t;
        __syncthreads();
        #pragma unroll
        for (int s = 64; s > 0; s >>= 1) {
            if (t < s) {
                float ov = redv[t + s]; int oi = redi[t + s];
                if (ov > redv[t] || (ov == redv[t] && oi < redi[t])) { redv[t] = ov; redi[t] = oi; }
            }
            __syncthreads();
        }
        if (t == 0) { s2sel[r] = redv[0]; i2sel[r] = redi[0]; wv[redi[0]] = -1e30f; }
        __syncthreads();
    }

    // 64 pairwise candidates (flattened order k1*8+k2 matches reference reshape)
    if (t < 64) {
        pv[t]   = __fadd_rn(s1sel[t >> 3], s2sel[t & 7]);
        pidx[t] = i1sel[t >> 3] * NKEY + i2sel[t & 7];
    }
    __syncthreads();

    // top-8 of 64 pairs
    for (int r = 0; r < TOPK; r++) {
        redv[t] = (t < 64) ? pv[t] : -1e30f;
        redi[t] = t;
        __syncthreads();
        #pragma unroll
        for (int s = 64; s > 0; s >>= 1) {
            if (t < s) {
                float ov = redv[t + s]; int oi = redi[t + s];
                if (ov > redv[t] || (ov == redv[t] && oi < redi[t])) { redv[t] = ov; redi[t] = oi; }
            }
            __syncthreads();
        }
        if (t == 0) {
            g_scores [((size_t)bt * NH + h) * TOPK + r] = redv[0];
            g_indices[((size_t)bt * NH + h) * TOPK + r] = pidx[redi[0]];
            pv[redi[0]] = -1e30f;
        }
        __syncthreads();
    }
}

// ---------------------------------------------------------------------------
// K3: per token: gather 32 expert rows from e_down, dot with x -> silu * relu(score),
//     then accumulate gated e_up rows into out. 1 block of 256 threads per token.
// ---------------------------------------------------------------------------
__global__ __launch_bounds__(256) void expert_kernel(const float* __restrict__ x,
                                                     const float* __restrict__ e_down,
                                                     const float* __restrict__ e_up,
                                                     float* __restrict__ out) {
    const int bt   = blockIdx.x;
    const int t    = threadIdx.x;
    const int warp = t >> 5;
    const int lane = t & 31;

    __shared__ __align__(16) float xs[DIM];
    __shared__ float gco[32];
    __shared__ int   gix[32];
    __shared__ float gsc[32];

    // stage x row (8 KB)
    const float4* x4  = (const float4*)(x + (size_t)bt * DIM);
    float4*       xs4 = (float4*)xs;
    xs4[t]       = x4[t];
    xs4[t + 256] = x4[t + 256];
    if (t < 32) {
        gsc[t] = fmaxf(g_scores[(size_t)bt * 32 + t], 0.f);
        gix[t] = g_indices[(size_t)bt * 32 + t];
    }
    __syncthreads();

    // Pass A: 8 warps x 4 experts — dot(x, e_down[idx]) -> gate coefficient
    #pragma unroll
    for (int ee = 0; ee < 4; ee++) {
        const int e = warp * 4 + ee;
        const float4* row = (const float4*)(e_down + (size_t)gix[e] * DIM);
        float a0 = 0.f, a1 = 0.f, a2 = 0.f, a3 = 0.f;
        #pragma unroll
        for (int i = 0; i < 16; i += 4) {
            float4 xa = xs4[lane + (i + 0) * 32], ra = row[lane + (i + 0) * 32];
            float4 xb = xs4[lane + (i + 1) * 32], rb = row[lane + (i + 1) * 32];
            float4 xc = xs4[lane + (i + 2) * 32], rc = row[lane + (i + 2) * 32];
            float4 xd = xs4[lane + (i + 3) * 32], rd = row[lane + (i + 3) * 32];
            a0 += xa.x * ra.x + xa.y * ra.y + xa.z * ra.z + xa.w * ra.w;
            a1 += xb.x * rb.x + xb.y * rb.y + xb.z * rb.z + xb.w * rb.w;
            a2 += xc.x * rc.x + xc.y * rc.y + xc.z * rc.z + xc.w * rc.w;
            a3 += xd.x * rd.x + xd.y * rd.y + xd.z * rd.z + xd.w * rd.w;
        }
        float acc = (a0 + a1) + (a2 + a3);
        #pragma unroll
        for (int s = 16; s > 0; s >>= 1) acc += __shfl_xor_sync(0xffffffffu, acc, s);
        if (lane == 0) {
            float sig = 1.f / (1.f + expf(-acc));
            gco[e] = acc * sig * gsc[e];   // silu(dot) * relu(score)
        }
    }
    __syncthreads();

    // Pass B: out[d] = sum_e gco[e] * e_up[idx_e][d]; each thread owns 2 float4s
    float4 o0 = make_float4(0.f, 0.f, 0.f, 0.f);
    float4 o1 = make_float4(0.f, 0.f, 0.f, 0.f);
    #pragma unroll 4
    for (int e = 0; e < 32; e++) {
        const float gc = gco[e];
        const float4* up = (const float4*)(e_up + (size_t)gix[e] * DIM);
        float4 u0 = up[t];
        float4 u1 = up[t + 256];
        o0.x += gc * u0.x; o0.y += gc * u0.y; o0.z += gc * u0.z; o0.w += gc * u0.w;
        o1.x += gc * u1.x; o1.y += gc * u1.y; o1.z += gc * u1.z; o1.w += gc * u1.w;
    }
    float4* o4 = (float4*)(out + (size_t)bt * DIM);
    o4[t]       = o0;
    o4[t + 256] = o1;
}

// ---------------------------------------------------------------------------
extern "C" void kernel_launch(void* const* d_in, const int* in_sizes, int n_in,
                              void* d_out, int out_size) {
    const float* x      = (const float*)d_in[0];
    const float* Wq     = (const float*)d_in[1];
    const float* keys   = (const float*)d_in[2];
    const float* e_down = (const float*)d_in[3];
    const float* e_up   = (const float*)d_in[4];
    float* out = (float*)d_out;

    qproj_kernel<<<dim3(QC / 64, BT / 64), 256>>>(x, Wq);
    route_kernel<<<BT * NH, 128>>>(keys);
    expert_kernel<<<BT, 256>>>(x, e_down, e_up, out);
}

// round 7
// speedup vs baseline: 1.7592x; 1.7592x over previous
#include <cuda_runtime.h>
#include <math.h>

// Problem constants
#define BT   2048      // B*T
#define DIM  2048      // D
#define NH   4         // H
#define TOPK 8         // K
#define DK   64
#define NKEY 128       // NK
#define QC   512       // 2*H*DK

// Scratch (device globals — no allocation allowed)
__device__ float g_q[BT * QC];                 // 4 MB
__device__ float g_sims[BT * NH * 2 * NKEY];   // 8 MB
__device__ float g_scores[BT * NH * TOPK];
__device__ int   g_indices[BT * NH * TOPK];

// ---- packed f32x2 helpers (sm_100+) --------------------------------------
#define FMA2(acc, a, b) asm("fma.rn.f32x2 %0, %1, %2, %0;" : "+l"(acc) : "l"(a), "l"(b))
#define ADD2(d, a, b)   asm("add.rn.f32x2 %0, %1, %2;" : "=l"(d) : "l"(a), "l"(b))
#define SUB2(d, a, b)   asm("sub.rn.f32x2 %0, %1, %2;" : "=l"(d) : "l"(a), "l"(b))
#define DUP2(d, s)      asm("mov.b64 %0, {%1, %1};"    : "=l"(d) : "f"(s))

// ---------------------------------------------------------------------------
// K1: q = x @ Wq  (M=2048, N=512, K=2048) fp32, 64x64 tile, 4x4/thread,
// packed f32x2 FFMA. KTILE=32 with register prefetch (software pipeline).
// Precision: two interleaved chains of 16 per tile + Kahan combine (rn ops),
// matching Round-4 numerics so the routing top-k selection is preserved.
// ---------------------------------------------------------------------------
__global__ __launch_bounds__(256) void qproj_kernel(const float* __restrict__ A,
                                                    const float* __restrict__ Bm) {
    __shared__ __align__(16) float As[32][68];   // k-major (transposed)
    __shared__ __align__(16) float Bs[32][68];

    const int t  = threadIdx.x;
    const int m0 = blockIdx.y * 64;
    const int n0 = blockIdx.x * 64;
    const int cx = t & 15;          // col group (4 cols)
    const int cy = t >> 4;          // row group (4 rows)
    const int ar = t >> 3, ac = t & 7;     // A-load: rows 0..31 (+32), 8 f4/row
    const int br = t >> 4, bc = t & 15;    // B-load: k 0..15 (+16), 16 f4/row

    const float* Ap0 = A  + (size_t)(m0 + ar)      * DIM + ac * 4;
    const float* Ap1 = A  + (size_t)(m0 + ar + 32) * DIM + ac * 4;
    const float* Bp0 = Bm + (size_t)(br)      * QC + n0 + bc * 4;
    const float* Bp1 = Bm + (size_t)(br + 16) * QC + n0 + bc * 4;

    unsigned long long acc[8], cmp[8];   // [i*2 + jp], each packs 2 cols
    #pragma unroll
    for (int e = 0; e < 8; e++) { acc[e] = 0ull; cmp[e] = 0ull; }

    float4 pa0 = *(const float4*)(Ap0);
    float4 pa1 = *(const float4*)(Ap1);
    float4 pb0 = *(const float4*)(Bp0);
    float4 pb1 = *(const float4*)(Bp1);

    for (int k0 = 0; k0 < DIM; k0 += 32) {
        // stage prefetched tile into smem
        As[ac * 4 + 0][ar] = pa0.x;  As[ac * 4 + 1][ar] = pa0.y;
        As[ac * 4 + 2][ar] = pa0.z;  As[ac * 4 + 3][ar] = pa0.w;
        As[ac * 4 + 0][ar + 32] = pa1.x;  As[ac * 4 + 1][ar + 32] = pa1.y;
        As[ac * 4 + 2][ar + 32] = pa1.z;  As[ac * 4 + 3][ar + 32] = pa1.w;
        *(float4*)&Bs[br][bc * 4]      = pb0;
        *(float4*)&Bs[br + 16][bc * 4] = pb1;
        __syncthreads();

        if (k0 + 32 < DIM) {   // issue next tile's LDGs; overlap with compute
            pa0 = *(const float4*)(Ap0 + k0 + 32);
            pa1 = *(const float4*)(Ap1 + k0 + 32);
            pb0 = *(const float4*)(Bp0 + (size_t)(k0 + 32) * QC);
            pb1 = *(const float4*)(Bp1 + (size_t)(k0 + 32) * QC);
        }

        // two interleaved chains (even/odd kk), 16 deep each
        unsigned long long ta[8], tb[8];
        #pragma unroll
        for (int e = 0; e < 8; e++) { ta[e] = 0ull; tb[e] = 0ull; }

        #pragma unroll
        for (int kk = 0; kk < 32; kk += 2) {
            float4 a0 = *(const float4*)&As[kk][cy * 4];
            ulonglong2 b0 = *(const ulonglong2*)&Bs[kk][cx * 4];
            float4 a1 = *(const float4*)&As[kk + 1][cy * 4];
            ulonglong2 b1 = *(const ulonglong2*)&Bs[kk + 1][cx * 4];
            unsigned long long d;
            DUP2(d, a0.x); FMA2(ta[0], d, b0.x); FMA2(ta[1], d, b0.y);
            DUP2(d, a0.y); FMA2(ta[2], d, b0.x); FMA2(ta[3], d, b0.y);
            DUP2(d, a0.z); FMA2(ta[4], d, b0.x); FMA2(ta[5], d, b0.y);
            DUP2(d, a0.w); FMA2(ta[6], d, b0.x); FMA2(ta[7], d, b0.y);
            DUP2(d, a1.x); FMA2(tb[0], d, b1.x); FMA2(tb[1], d, b1.y);
            DUP2(d, a1.y); FMA2(tb[2], d, b1.x); FMA2(tb[3], d, b1.y);
            DUP2(d, a1.z); FMA2(tb[4], d, b1.x); FMA2(tb[5], d, b1.y);
            DUP2(d, a1.w); FMA2(tb[6], d, b1.x); FMA2(tb[7], d, b1.y);
        }
        __syncthreads();

        // Kahan combine (packed, round-to-nearest, opaque to compiler)
        #pragma unroll
        for (int e = 0; e < 8; e++) {
            unsigned long long ts, y, t2, z;
            ADD2(ts, ta[e], tb[e]);
            SUB2(y, ts, cmp[e]);
            ADD2(t2, acc[e], y);
            SUB2(z, t2, acc[e]);
            SUB2(cmp[e], z, y);
            acc[e] = t2;
        }
    }

    #pragma unroll
    for (int i = 0; i < 4; i++) {
        ulonglong2 o;
        o.x = acc[i * 2 + 0];
        o.y = acc[i * 2 + 1];
        *(ulonglong2*)(&g_q[(size_t)(m0 + cy * 4 + i) * QC + n0 + cx * 4]) = o;
    }
}

// ---------------------------------------------------------------------------
// K2a: sims[bt][h][half][k] = dot(q[bt,h,half,:], keys[h,k,half,:])
// Block = (token-tile of 128) x h x half. Keys staged in smem (broadcast LDS),
// q row in registers, output transposed through smem for coalesced stores.
// Dot summation order replicates Round-4 route (4 chains of 16, rn combine).
// ---------------------------------------------------------------------------
__global__ __launch_bounds__(128) void sim_kernel(const float* __restrict__ keys) {
    const int tile = blockIdx.x;   // 0..15
    const int h    = blockIdx.y;   // 0..3
    const int half = blockIdx.z;   // 0..1
    const int t    = threadIdx.x;

    __shared__ __align__(16) float ks[NKEY][DK];   // 32 KB
    __shared__ float sbuf[128][17];                // 8.5 KB (16-key chunks)

    // stage keys for (h, half): 2048 float4s, coalesced
    const float4* kg = (const float4*)keys;
    #pragma unroll
    for (int i = 0; i < 16; i++) {
        int l = t + 128 * i;
        int k = l >> 4, c4 = l & 15;
        ((float4*)&ks[k][0])[c4] = kg[((size_t)(h * NKEY + k) * 2 + half) * 16 + c4];
    }

    // q row for this thread's token (64 floats in registers)
    const int token = tile * 128 + t;
    float4 qr[16];
    const float4* qg = (const float4*)(g_q + (size_t)token * QC + h * 128 + half * 64);
    #pragma unroll
    for (int i = 0; i < 16; i++) qr[i] = qg[i];
    __syncthreads();

    for (int kc = 0; kc < NKEY; kc += 16) {
        #pragma unroll
        for (int k = 0; k < 16; k++) {
            const float4* kr = (const float4*)&ks[kc + k][0];
            float p0 = 0.f, p1 = 0.f, p2 = 0.f, p3 = 0.f;
            #pragma unroll
            for (int i = 0; i < 16; i += 4) {
                float4 a, b;
                a = qr[i + 0]; b = kr[i + 0];
                p0 = fmaf(a.x, b.x, fmaf(a.y, b.y, fmaf(a.z, b.z, fmaf(a.w, b.w, p0))));
                a = qr[i + 1]; b = kr[i + 1];
                p1 = fmaf(a.x, b.x, fmaf(a.y, b.y, fmaf(a.z, b.z, fmaf(a.w, b.w, p1))));
                a = qr[i + 2]; b = kr[i + 2];
                p2 = fmaf(a.x, b.x, fmaf(a.y, b.y, fmaf(a.z, b.z, fmaf(a.w, b.w, p2))));
                a = qr[i + 3]; b = kr[i + 3];
                p3 = fmaf(a.x, b.x, fmaf(a.y, b.y, fmaf(a.z, b.z, fmaf(a.w, b.w, p3))));
            }
            sbuf[t][k] = __fadd_rn(__fadd_rn(p0, p1), __fadd_rn(p2, p3));
        }
        __syncthreads();
        // coalesced store of the 128x16 chunk
        #pragma unroll
        for (int i = 0; i < 16; i++) {
            int l = t + 128 * i;
            int tok = l >> 4, kk = l & 15;
            g_sims[((size_t)(tile * 128 + tok) * NH + h) * 256 + half * NKEY + kc + kk]
                = sbuf[tok][kk];
        }
        __syncthreads();
    }
}

// ---------------------------------------------------------------------------
// K2b: warp-level top-k. One warp per (bt,h): top-8 per half (128 keys),
// 64 pair sums, top-8 of pairs. Shfl-butterfly argmax, lowest-index tiebreak
// (matches jax.lax.top_k). No __syncthreads.
// ---------------------------------------------------------------------------
__global__ __launch_bounds__(256) void topk_kernel() {
    const int w    = threadIdx.x >> 5;
    const int lane = threadIdx.x & 31;
    const int gw   = blockIdx.x * 8 + w;    // 0..8191 = bt*4 + h

    __shared__ __align__(16) float sv[8][256];
    __shared__ float s1s[8][8], s2s[8][8];
    __shared__ int   i1s[8][8], i2s[8][8];
    __shared__ float pv[8][64];
    __shared__ int   pix[8][64];

    const float4* sg = (const float4*)(g_sims + (size_t)gw * 256);
    ((float4*)sv[w])[lane]      = sg[lane];
    ((float4*)sv[w])[lane + 32] = sg[lane + 32];
    __syncwarp();

    // --- top-8 of each half ---
    #pragma unroll
    for (int hf = 0; hf < 2; hf++) {
        float* base = sv[w] + hf * 128;
        #pragma unroll
        for (int r = 0; r < 8; r++) {
            float v = base[lane];        int idx = lane;
            float v1 = base[lane + 32];  if (v1 > v) { v = v1; idx = lane + 32; }
            float v2 = base[lane + 64];  if (v2 > v) { v = v2; idx = lane + 64; }
            float v3 = base[lane + 96];  if (v3 > v) { v = v3; idx = lane + 96; }
            #pragma unroll
            for (int s = 16; s > 0; s >>= 1) {
                float ov = __shfl_xor_sync(0xffffffffu, v, s);
                int   oi = __shfl_xor_sync(0xffffffffu, idx, s);
                if (ov > v || (ov == v && oi < idx)) { v = ov; idx = oi; }
            }
            if (lane == 0) {
                if (hf == 0) { s1s[w][r] = v; i1s[w][r] = idx; }
                else         { s2s[w][r] = v; i2s[w][r] = idx; }
                base[idx] = -1e30f;
            }
            __syncwarp();
        }
    }

    // --- 64 pair candidates (flat order a*8+b matches reference reshape) ---
    #pragma unroll
    for (int pp = 0; pp < 2; pp++) {
        int p = lane + pp * 32;
        pv[w][p]  = __fadd_rn(s1s[w][p >> 3], s2s[w][p & 7]);
        pix[w][p] = i1s[w][p >> 3] * NKEY + i2s[w][p & 7];
    }
    __syncwarp();

    // --- top-8 of pairs ---
    #pragma unroll
    for (int r = 0; r < 8; r++) {
        float v = pv[w][lane];        int idx = lane;
        float v1 = pv[w][lane + 32];  if (v1 > v) { v = v1; idx = lane + 32; }
        #pragma unroll
        for (int s = 16; s > 0; s >>= 1) {
            float ov = __shfl_xor_sync(0xffffffffu, v, s);
            int   oi = __shfl_xor_sync(0xffffffffu, idx, s);
            if (ov > v || (ov == v && oi < idx)) { v = ov; idx = oi; }
        }
        if (lane == 0) {
            g_scores [(size_t)gw * TOPK + r] = v;
            g_indices[(size_t)gw * TOPK + r] = pix[w][idx];
            pv[w][idx] = -1e30f;
        }
        __syncwarp();
    }
}

// ---------------------------------------------------------------------------
// K3: per token: gather 32 expert rows from e_down, dot with x -> silu * relu(score),
//     then accumulate gated e_up rows into out. 1 block of 256 threads per token.
// ---------------------------------------------------------------------------
__global__ __launch_bounds__(256) void expert_kernel(const float* __restrict__ x,
                                                     const float* __restrict__ e_down,
                                                     const float* __restrict__ e_up,
                                                     float* __restrict__ out) {
    const int bt   = blockIdx.x;
    const int t    = threadIdx.x;
    const int warp = t >> 5;
    const int lane = t & 31;

    __shared__ __align__(16) float xs[DIM];
    __shared__ float gco[32];
    __shared__ int   gix[32];
    __shared__ float gsc[32];

    // stage x row (8 KB)
    const float4* x4  = (const float4*)(x + (size_t)bt * DIM);
    float4*       xs4 = (float4*)xs;
    xs4[t]       = x4[t];
    xs4[t + 256] = x4[t + 256];
    if (t < 32) {
        gsc[t] = fmaxf(g_scores[(size_t)bt * 32 + t], 0.f);
        gix[t] = g_indices[(size_t)bt * 32 + t];
    }
    __syncthreads();

    // Pass A: 8 warps x 4 experts — dot(x, e_down[idx]) -> gate coefficient
    #pragma unroll
    for (int ee = 0; ee < 4; ee++) {
        const int e = warp * 4 + ee;
        const float4* row = (const float4*)(e_down + (size_t)gix[e] * DIM);
        float a0 = 0.f, a1 = 0.f, a2 = 0.f, a3 = 0.f;
        #pragma unroll
        for (int i = 0; i < 16; i += 4) {
            float4 xa = xs4[lane + (i + 0) * 32], ra = row[lane + (i + 0) * 32];
            float4 xb = xs4[lane + (i + 1) * 32], rb = row[lane + (i + 1) * 32];
            float4 xc = xs4[lane + (i + 2) * 32], rc = row[lane + (i + 2) * 32];
            float4 xd = xs4[lane + (i + 3) * 32], rd = row[lane + (i + 3) * 32];
            a0 += xa.x * ra.x + xa.y * ra.y + xa.z * ra.z + xa.w * ra.w;
            a1 += xb.x * rb.x + xb.y * rb.y + xb.z * rb.z + xb.w * rb.w;
            a2 += xc.x * rc.x + xc.y * rc.y + xc.z * rc.z + xc.w * rc.w;
            a3 += xd.x * rd.x + xd.y * rd.y + xd.z * rd.z + xd.w * rd.w;
        }
        float acc = (a0 + a1) + (a2 + a3);
        #pragma unroll
        for (int s = 16; s > 0; s >>= 1) acc += __shfl_xor_sync(0xffffffffu, acc, s);
        if (lane == 0) {
            float sig = 1.f / (1.f + expf(-acc));
            gco[e] = acc * sig * gsc[e];   // silu(dot) * relu(score)
        }
    }
    __syncthreads();

    // Pass B: out[d] = sum_e gco[e] * e_up[idx_e][d]; each thread owns 2 float4s
    float4 o0 = make_float4(0.f, 0.f, 0.f, 0.f);
    float4 o1 = make_float4(0.f, 0.f, 0.f, 0.f);
    #pragma unroll 8
    for (int e = 0; e < 32; e++) {
        const float gc = gco[e];
        const float4* up = (const float4*)(e_up + (size_t)gix[e] * DIM);
        float4 u0 = up[t];
        float4 u1 = up[t + 256];
        o0.x += gc * u0.x; o0.y += gc * u0.y; o0.z += gc * u0.z; o0.w += gc * u0.w;
        o1.x += gc * u1.x; o1.y += gc * u1.y; o1.z += gc * u1.z; o1.w += gc * u1.w;
    }
    float4* o4 = (float4*)(out + (size_t)bt * DIM);
    o4[t]       = o0;
    o4[t + 256] = o1;
}

// ---------------------------------------------------------------------------
extern "C" void kernel_launch(void* const* d_in, const int* in_sizes, int n_in,
                              void* d_out, int out_size) {
    const float* x      = (const float*)d_in[0];
    const float* Wq     = (const float*)d_in[1];
    const float* keys   = (const float*)d_in[2];
    const float* e_down = (const float*)d_in[3];
    const float* e_up   = (const float*)d_in[4];
    float* out = (float*)d_out;

    qproj_kernel<<<dim3(QC / 64, BT / 64), 256>>>(x, Wq);
    sim_kernel<<<dim3(BT / 128, NH, 2), 128>>>(keys);
    topk_kernel<<<BT * NH / 8, 256>>>();
    expert_kernel<<<BT, 256>>>(x, e_down, e_up, out);
}

// round 9
// speedup vs baseline: 2.0143x; 1.1450x over previous
#include <cuda_runtime.h>
#include <math.h>

// Problem constants
#define BT   2048      // B*T
#define DIM  2048      // D
#define NH   4         // H
#define TOPK 8         // K
#define DK   64
#define NKEY 128       // NK
#define QC   512       // 2*H*DK

// Scratch (device globals — no allocation allowed)
__device__ float g_q[BT * QC];                 // 4 MB
__device__ float g_sims[BT * NH * 2 * NKEY];   // 8 MB
__device__ float g_scores[BT * NH * TOPK];
__device__ int   g_indices[BT * NH * TOPK];
__device__ float g_gco[BT * 32];               // gate coefficients

// ---- packed f32x2 helpers (sm_100+) --------------------------------------
#define FMA2(acc, a, b) asm("fma.rn.f32x2 %0, %1, %2, %0;" : "+l"(acc) : "l"(a), "l"(b))
#define ADD2(d, a, b)   asm("add.rn.f32x2 %0, %1, %2;" : "=l"(d) : "l"(a), "l"(b))
#define SUB2(d, a, b)   asm("sub.rn.f32x2 %0, %1, %2;" : "=l"(d) : "l"(a), "l"(b))
#define DUP2(d, s)      asm("mov.b64 %0, {%1, %1};"    : "=l"(d) : "f"(s))

// ---------------------------------------------------------------------------
// K1: q = x @ Wq  (M=2048, N=512, K=2048) fp32, 64x64 tile, 4x4/thread,
// packed f32x2 FFMA. KTILE=32 with register prefetch (software pipeline).
// Precision: two interleaved chains of 16 per tile + Kahan combine (rn ops).
// ---------------------------------------------------------------------------
__global__ __launch_bounds__(256) void qproj_kernel(const float* __restrict__ A,
                                                    const float* __restrict__ Bm) {
    __shared__ __align__(16) float As[32][68];   // k-major (transposed)
    __shared__ __align__(16) float Bs[32][68];

    const int t  = threadIdx.x;
    const int m0 = blockIdx.y * 64;
    const int n0 = blockIdx.x * 64;
    const int cx = t & 15;          // col group (4 cols)
    const int cy = t >> 4;          // row group (4 rows)
    const int ar = t >> 3, ac = t & 7;     // A-load: rows 0..31 (+32), 8 f4/row
    const int br = t >> 4, bc = t & 15;    // B-load: k 0..15 (+16), 16 f4/row

    const float* Ap0 = A  + (size_t)(m0 + ar)      * DIM + ac * 4;
    const float* Ap1 = A  + (size_t)(m0 + ar + 32) * DIM + ac * 4;
    const float* Bp0 = Bm + (size_t)(br)      * QC + n0 + bc * 4;
    const float* Bp1 = Bm + (size_t)(br + 16) * QC + n0 + bc * 4;

    unsigned long long acc[8], cmp[8];   // [i*2 + jp], each packs 2 cols
    #pragma unroll
    for (int e = 0; e < 8; e++) { acc[e] = 0ull; cmp[e] = 0ull; }

    float4 pa0 = *(const float4*)(Ap0);
    float4 pa1 = *(const float4*)(Ap1);
    float4 pb0 = *(const float4*)(Bp0);
    float4 pb1 = *(const float4*)(Bp1);

    for (int k0 = 0; k0 < DIM; k0 += 32) {
        As[ac * 4 + 0][ar] = pa0.x;  As[ac * 4 + 1][ar] = pa0.y;
        As[ac * 4 + 2][ar] = pa0.z;  As[ac * 4 + 3][ar] = pa0.w;
        As[ac * 4 + 0][ar + 32] = pa1.x;  As[ac * 4 + 1][ar + 32] = pa1.y;
        As[ac * 4 + 2][ar + 32] = pa1.z;  As[ac * 4 + 3][ar + 32] = pa1.w;
        *(float4*)&Bs[br][bc * 4]      = pb0;
        *(float4*)&Bs[br + 16][bc * 4] = pb1;
        __syncthreads();

        if (k0 + 32 < DIM) {   // issue next tile's LDGs; overlap with compute
            pa0 = *(const float4*)(Ap0 + k0 + 32);
            pa1 = *(const float4*)(Ap1 + k0 + 32);
            pb0 = *(const float4*)(Bp0 + (size_t)(k0 + 32) * QC);
            pb1 = *(const float4*)(Bp1 + (size_t)(k0 + 32) * QC);
        }

        unsigned long long ta[8], tb[8];
        #pragma unroll
        for (int e = 0; e < 8; e++) { ta[e] = 0ull; tb[e] = 0ull; }

        #pragma unroll
        for (int kk = 0; kk < 32; kk += 2) {
            float4 a0 = *(const float4*)&As[kk][cy * 4];
            ulonglong2 b0 = *(const ulonglong2*)&Bs[kk][cx * 4];
            float4 a1 = *(const float4*)&As[kk + 1][cy * 4];
            ulonglong2 b1 = *(const ulonglong2*)&Bs[kk + 1][cx * 4];
            unsigned long long d;
            DUP2(d, a0.x); FMA2(ta[0], d, b0.x); FMA2(ta[1], d, b0.y);
            DUP2(d, a0.y); FMA2(ta[2], d, b0.x); FMA2(ta[3], d, b0.y);
            DUP2(d, a0.z); FMA2(ta[4], d, b0.x); FMA2(ta[5], d, b0.y);
            DUP2(d, a0.w); FMA2(ta[6], d, b0.x); FMA2(ta[7], d, b0.y);
            DUP2(d, a1.x); FMA2(tb[0], d, b1.x); FMA2(tb[1], d, b1.y);
            DUP2(d, a1.y); FMA2(tb[2], d, b1.x); FMA2(tb[3], d, b1.y);
            DUP2(d, a1.z); FMA2(tb[4], d, b1.x); FMA2(tb[5], d, b1.y);
            DUP2(d, a1.w); FMA2(tb[6], d, b1.x); FMA2(tb[7], d, b1.y);
        }
        __syncthreads();

        #pragma unroll
        for (int e = 0; e < 8; e++) {
            unsigned long long ts, y, t2, z;
            ADD2(ts, ta[e], tb[e]);
            SUB2(y, ts, cmp[e]);
            ADD2(t2, acc[e], y);
            SUB2(z, t2, acc[e]);
            SUB2(cmp[e], z, y);
            acc[e] = t2;
        }
    }

    #pragma unroll
    for (int i = 0; i < 4; i++) {
        ulonglong2 o;
        o.x = acc[i * 2 + 0];
        o.y = acc[i * 2 + 1];
        *(ulonglong2*)(&g_q[(size_t)(m0 + cy * 4 + i) * QC + n0 + cx * 4]) = o;
    }
}

// ---------------------------------------------------------------------------
// K2a: sims[bt][h][half][k] = dot(q[bt,h,half,:], keys[h,k,half,:])
// ---------------------------------------------------------------------------
__global__ __launch_bounds__(128) void sim_kernel(const float* __restrict__ keys) {
    const int tile = blockIdx.x;   // 0..15
    const int h    = blockIdx.y;   // 0..3
    const int half = blockIdx.z;   // 0..1
    const int t    = threadIdx.x;

    __shared__ __align__(16) float ks[NKEY][DK];   // 32 KB
    __shared__ float sbuf[128][17];                // 8.5 KB (16-key chunks)

    const float4* kg = (const float4*)keys;
    #pragma unroll
    for (int i = 0; i < 16; i++) {
        int l = t + 128 * i;
        int k = l >> 4, c4 = l & 15;
        ((float4*)&ks[k][0])[c4] = kg[((size_t)(h * NKEY + k) * 2 + half) * 16 + c4];
    }

    const int token = tile * 128 + t;
    float4 qr[16];
    const float4* qg = (const float4*)(g_q + (size_t)token * QC + h * 128 + half * 64);
    #pragma unroll
    for (int i = 0; i < 16; i++) qr[i] = qg[i];
    __syncthreads();

    for (int kc = 0; kc < NKEY; kc += 16) {
        #pragma unroll
        for (int k = 0; k < 16; k++) {
            const float4* kr = (const float4*)&ks[kc + k][0];
            float p0 = 0.f, p1 = 0.f, p2 = 0.f, p3 = 0.f;
            #pragma unroll
            for (int i = 0; i < 16; i += 4) {
                float4 a, b;
                a = qr[i + 0]; b = kr[i + 0];
                p0 = fmaf(a.x, b.x, fmaf(a.y, b.y, fmaf(a.z, b.z, fmaf(a.w, b.w, p0))));
                a = qr[i + 1]; b = kr[i + 1];
                p1 = fmaf(a.x, b.x, fmaf(a.y, b.y, fmaf(a.z, b.z, fmaf(a.w, b.w, p1))));
                a = qr[i + 2]; b = kr[i + 2];
                p2 = fmaf(a.x, b.x, fmaf(a.y, b.y, fmaf(a.z, b.z, fmaf(a.w, b.w, p2))));
                a = qr[i + 3]; b = kr[i + 3];
                p3 = fmaf(a.x, b.x, fmaf(a.y, b.y, fmaf(a.z, b.z, fmaf(a.w, b.w, p3))));
            }
            sbuf[t][k] = __fadd_rn(__fadd_rn(p0, p1), __fadd_rn(p2, p3));
        }
        __syncthreads();
        #pragma unroll
        for (int i = 0; i < 16; i++) {
            int l = t + 128 * i;
            int tok = l >> 4, kk = l & 15;
            g_sims[((size_t)(tile * 128 + tok) * NH + h) * 256 + half * NKEY + kc + kk]
                = sbuf[tok][kk];
        }
        __syncthreads();
    }
}

// ---------------------------------------------------------------------------
// K2b: warp-level top-k. One warp per (bt,h).
// ---------------------------------------------------------------------------
__global__ __launch_bounds__(256) void topk_kernel() {
    const int w    = threadIdx.x >> 5;
    const int lane = threadIdx.x & 31;
    const int gw   = blockIdx.x * 8 + w;    // 0..8191 = bt*4 + h

    __shared__ __align__(16) float sv[8][256];
    __shared__ float s1s[8][8], s2s[8][8];
    __shared__ int   i1s[8][8], i2s[8][8];
    __shared__ float pv[8][64];
    __shared__ int   pix[8][64];

    const float4* sg = (const float4*)(g_sims + (size_t)gw * 256);
    ((float4*)sv[w])[lane]      = sg[lane];
    ((float4*)sv[w])[lane + 32] = sg[lane + 32];
    __syncwarp();

    #pragma unroll
    for (int hf = 0; hf < 2; hf++) {
        float* base = sv[w] + hf * 128;
        #pragma unroll
        for (int r = 0; r < 8; r++) {
            float v = base[lane];        int idx = lane;
            float v1 = base[lane + 32];  if (v1 > v) { v = v1; idx = lane + 32; }
            float v2 = base[lane + 64];  if (v2 > v) { v = v2; idx = lane + 64; }
            float v3 = base[lane + 96];  if (v3 > v) { v = v3; idx = lane + 96; }
            #pragma unroll
            for (int s = 16; s > 0; s >>= 1) {
                float ov = __shfl_xor_sync(0xffffffffu, v, s);
                int   oi = __shfl_xor_sync(0xffffffffu, idx, s);
                if (ov > v || (ov == v && oi < idx)) { v = ov; idx = oi; }
            }
            if (lane == 0) {
                if (hf == 0) { s1s[w][r] = v; i1s[w][r] = idx; }
                else         { s2s[w][r] = v; i2s[w][r] = idx; }
                base[idx] = -1e30f;
            }
            __syncwarp();
        }
    }

    #pragma unroll
    for (int pp = 0; pp < 2; pp++) {
        int p = lane + pp * 32;
        pv[w][p]  = __fadd_rn(s1s[w][p >> 3], s2s[w][p & 7]);
        pix[w][p] = i1s[w][p >> 3] * NKEY + i2s[w][p & 7];
    }
    __syncwarp();

    #pragma unroll
    for (int r = 0; r < 8; r++) {
        float v = pv[w][lane];        int idx = lane;
        float v1 = pv[w][lane + 32];  if (v1 > v) { v = v1; idx = lane + 32; }
        #pragma unroll
        for (int s = 16; s > 0; s >>= 1) {
            float ov = __shfl_xor_sync(0xffffffffu, v, s);
            int   oi = __shfl_xor_sync(0xffffffffu, idx, s);
            if (ov > v || (ov == v && oi < idx)) { v = ov; idx = oi; }
        }
        if (lane == 0) {
            g_scores [(size_t)gw * TOPK + r] = v;
            g_indices[(size_t)gw * TOPK + r] = pix[w][idx];
            pv[w][idx] = -1e30f;
        }
        __syncwarp();
    }
}

// ---------------------------------------------------------------------------
// K3a: gate — per token: dot(x, e_down[idx_e]) -> gco[e] = silu(dot)*relu(score).
// 1 block of 256 threads per token; 8 warps x 4 experts. Low regs -> high occ.
// Same summation structure as the passing Round-7 kernel (bit-identical).
// ---------------------------------------------------------------------------
__global__ __launch_bounds__(256) void gate_kernel(const float* __restrict__ x,
                                                   const float* __restrict__ e_down) {
    const int bt   = blockIdx.x;
    const int t    = threadIdx.x;
    const int warp = t >> 5;
    const int lane = t & 31;

    __shared__ __align__(16) float xs[DIM];
    __shared__ int   gix[32];
    __shared__ float gsc[32];

    const float4* x4  = (const float4*)(x + (size_t)bt * DIM);
    float4*       xs4 = (float4*)xs;
    xs4[t]       = x4[t];
    xs4[t + 256] = x4[t + 256];
    if (t < 32) {
        gsc[t] = fmaxf(g_scores[(size_t)bt * 32 + t], 0.f);
        gix[t] = g_indices[(size_t)bt * 32 + t];
    }
    __syncthreads();

    #pragma unroll
    for (int ee = 0; ee < 4; ee++) {
        const int e = warp * 4 + ee;
        const float4* row = (const float4*)(e_down + (size_t)gix[e] * DIM);
        float a0 = 0.f, a1 = 0.f, a2 = 0.f, a3 = 0.f;
        #pragma unroll
        for (int i = 0; i < 16; i += 4) {
            float4 xa = xs4[lane + (i + 0) * 32], ra = row[lane + (i + 0) * 32];
            float4 xb = xs4[lane + (i + 1) * 32], rb = row[lane + (i + 1) * 32];
            float4 xc = xs4[lane + (i + 2) * 32], rc = row[lane + (i + 2) * 32];
            float4 xd = xs4[lane + (i + 3) * 32], rd = row[lane + (i + 3) * 32];
            a0 += xa.x * ra.x + xa.y * ra.y + xa.z * ra.z + xa.w * ra.w;
            a1 += xb.x * rb.x + xb.y * rb.y + xb.z * rb.z + xb.w * rb.w;
            a2 += xc.x * rc.x + xc.y * rc.y + xc.z * rc.z + xc.w * rc.w;
            a3 += xd.x * rd.x + xd.y * rd.y + xd.z * rd.z + xd.w * rd.w;
        }
        float acc = (a0 + a1) + (a2 + a3);
        #pragma unroll
        for (int s = 16; s > 0; s >>= 1) acc += __shfl_xor_sync(0xffffffffu, acc, s);
        if (lane == 0) {
            float sig = 1.f / (1.f + expf(-acc));
            g_gco[(size_t)bt * 32 + e] = acc * sig * gsc[e];
        }
    }
}

// ---------------------------------------------------------------------------
// K3b: out — out[bt][d] = sum_e gco[e] * e_up[idx_e][d].
// Grid = (token, D-chunk of 1024). Block 256; 1 float4 per thread.
// Minimal registers -> ~5 blocks/SM; e-loop unrolled for 8+ outstanding LDGs.
// Accumulation order over e identical to Round-7 (bit-identical output).
// ---------------------------------------------------------------------------
__global__ __launch_bounds__(256) void out_kernel(const float* __restrict__ e_up,
                                                  float* __restrict__ out) {
    const int bt = blockIdx.x;
    const int c  = blockIdx.y;          // 0 or 1
    const int t  = threadIdx.x;

    __shared__ int   gix[32];
    __shared__ float gco[32];
    if (t < 32) {
        gix[t] = g_indices[(size_t)bt * 32 + t];
        gco[t] = g_gco[(size_t)bt * 32 + t];
    }
    __syncthreads();

    const int off = c * 256 + t;        // float4 index within the token row
    float4 o = make_float4(0.f, 0.f, 0.f, 0.f);
    #pragma unroll 8
    for (int e = 0; e < 32; e++) {
        const float gc = gco[e];
        float4 u = ((const float4*)(e_up + (size_t)gix[e] * DIM))[off];
        o.x += gc * u.x; o.y += gc * u.y; o.z += gc * u.z; o.w += gc * u.w;
    }
    ((float4*)(out + (size_t)bt * DIM))[off] = o;
}

// ---------------------------------------------------------------------------
extern "C" void kernel_launch(void* const* d_in, const int* in_sizes, int n_in,
                              void* d_out, int out_size) {
    const float* x      = (const float*)d_in[0];
    const float* Wq     = (const float*)d_in[1];
    const float* keys   = (const float*)d_in[2];
    const float* e_down = (const float*)d_in[3];
    const float* e_up   = (const float*)d_in[4];
    float* out = (float*)d_out;

    qproj_kernel<<<dim3(QC / 64, BT / 64), 256>>>(x, Wq);
    sim_kernel<<<dim3(BT / 128, NH, 2), 128>>>(keys);
    topk_kernel<<<BT * NH / 8, 256>>>();
    gate_kernel<<<BT, 256>>>(x, e_down);
    out_kernel<<<dim3(BT, 2), 256>>>(e_up, out);
}

// round 10
// speedup vs baseline: 2.3864x; 1.1847x over previous
#include <cuda_runtime.h>
#include <math.h>

// Problem constants
#define BT   2048      // B*T
#define DIM  2048      // D
#define NH   4         // H
#define TOPK 8         // K
#define DK   64
#define NKEY 128       // NK
#define QC   512       // 2*H*DK

// Scratch (device globals — no allocation allowed)
__device__ float g_q[BT * QC];                 // 4 MB
__device__ float g_sims[BT * NH * 2 * NKEY];   // 8 MB
__device__ float g_scores[BT * NH * TOPK];
__device__ int   g_indices[BT * NH * TOPK];
__device__ float g_gco[BT * 32];               // gate coefficients

// ---- packed f32x2 helpers (sm_100+) --------------------------------------
#define FMA2(acc, a, b) asm("fma.rn.f32x2 %0, %1, %2, %0;" : "+l"(acc) : "l"(a), "l"(b))
#define ADD2(d, a, b)   asm("add.rn.f32x2 %0, %1, %2;" : "=l"(d) : "l"(a), "l"(b))
#define SUB2(d, a, b)   asm("sub.rn.f32x2 %0, %1, %2;" : "=l"(d) : "l"(a), "l"(b))
#define DUP2(d, s)      asm("mov.b64 %0, {%1, %1};"    : "=l"(d) : "f"(s))

// ---------------------------------------------------------------------------
// K1: q = x @ Wq  (M=2048, N=512, K=2048) fp32, 64x64 tile, 4x4/thread,
// packed f32x2 FFMA. KTILE=32 with register prefetch (software pipeline).
// Precision: two interleaved chains of 16 per tile + Kahan combine (rn ops).
// ---------------------------------------------------------------------------
__global__ __launch_bounds__(256) void qproj_kernel(const float* __restrict__ A,
                                                    const float* __restrict__ Bm) {
    __shared__ __align__(16) float As[32][68];   // k-major (transposed)
    __shared__ __align__(16) float Bs[32][68];

    const int t  = threadIdx.x;
    const int m0 = blockIdx.y * 64;
    const int n0 = blockIdx.x * 64;
    const int cx = t & 15;          // col group (4 cols)
    const int cy = t >> 4;          // row group (4 rows)
    const int ar = t >> 3, ac = t & 7;     // A-load: rows 0..31 (+32), 8 f4/row
    const int br = t >> 4, bc = t & 15;    // B-load: k 0..15 (+16), 16 f4/row

    const float* Ap0 = A  + (size_t)(m0 + ar)      * DIM + ac * 4;
    const float* Ap1 = A  + (size_t)(m0 + ar + 32) * DIM + ac * 4;
    const float* Bp0 = Bm + (size_t)(br)      * QC + n0 + bc * 4;
    const float* Bp1 = Bm + (size_t)(br + 16) * QC + n0 + bc * 4;

    unsigned long long acc[8], cmp[8];   // [i*2 + jp], each packs 2 cols
    #pragma unroll
    for (int e = 0; e < 8; e++) { acc[e] = 0ull; cmp[e] = 0ull; }

    float4 pa0 = *(const float4*)(Ap0);
    float4 pa1 = *(const float4*)(Ap1);
    float4 pb0 = *(const float4*)(Bp0);
    float4 pb1 = *(const float4*)(Bp1);

    for (int k0 = 0; k0 < DIM; k0 += 32) {
        As[ac * 4 + 0][ar] = pa0.x;  As[ac * 4 + 1][ar] = pa0.y;
        As[ac * 4 + 2][ar] = pa0.z;  As[ac * 4 + 3][ar] = pa0.w;
        As[ac * 4 + 0][ar + 32] = pa1.x;  As[ac * 4 + 1][ar + 32] = pa1.y;
        As[ac * 4 + 2][ar + 32] = pa1.z;  As[ac * 4 + 3][ar + 32] = pa1.w;
        *(float4*)&Bs[br][bc * 4]      = pb0;
        *(float4*)&Bs[br + 16][bc * 4] = pb1;
        __syncthreads();

        if (k0 + 32 < DIM) {   // issue next tile's LDGs; overlap with compute
            pa0 = *(const float4*)(Ap0 + k0 + 32);
            pa1 = *(const float4*)(Ap1 + k0 + 32);
            pb0 = *(const float4*)(Bp0 + (size_t)(k0 + 32) * QC);
            pb1 = *(const float4*)(Bp1 + (size_t)(k0 + 32) * QC);
        }

        unsigned long long ta[8], tb[8];
        #pragma unroll
        for (int e = 0; e < 8; e++) { ta[e] = 0ull; tb[e] = 0ull; }

        #pragma unroll
        for (int kk = 0; kk < 32; kk += 2) {
            float4 a0 = *(const float4*)&As[kk][cy * 4];
            ulonglong2 b0 = *(const ulonglong2*)&Bs[kk][cx * 4];
            float4 a1 = *(const float4*)&As[kk + 1][cy * 4];
            ulonglong2 b1 = *(const ulonglong2*)&Bs[kk + 1][cx * 4];
            unsigned long long d;
            DUP2(d, a0.x); FMA2(ta[0], d, b0.x); FMA2(ta[1], d, b0.y);
            DUP2(d, a0.y); FMA2(ta[2], d, b0.x); FMA2(ta[3], d, b0.y);
            DUP2(d, a0.z); FMA2(ta[4], d, b0.x); FMA2(ta[5], d, b0.y);
            DUP2(d, a0.w); FMA2(ta[6], d, b0.x); FMA2(ta[7], d, b0.y);
            DUP2(d, a1.x); FMA2(tb[0], d, b1.x); FMA2(tb[1], d, b1.y);
            DUP2(d, a1.y); FMA2(tb[2], d, b1.x); FMA2(tb[3], d, b1.y);
            DUP2(d, a1.z); FMA2(tb[4], d, b1.x); FMA2(tb[5], d, b1.y);
            DUP2(d, a1.w); FMA2(tb[6], d, b1.x); FMA2(tb[7], d, b1.y);
        }
        __syncthreads();

        #pragma unroll
        for (int e = 0; e < 8; e++) {
            unsigned long long ts, y, t2, z;
            ADD2(ts, ta[e], tb[e]);
            SUB2(y, ts, cmp[e]);
            ADD2(t2, acc[e], y);
            SUB2(z, t2, acc[e]);
            SUB2(cmp[e], z, y);
            acc[e] = t2;
        }
    }

    #pragma unroll
    for (int i = 0; i < 4; i++) {
        ulonglong2 o;
        o.x = acc[i * 2 + 0];
        o.y = acc[i * 2 + 1];
        *(ulonglong2*)(&g_q[(size_t)(m0 + cy * 4 + i) * QC + n0 + cx * 4]) = o;
    }
}

// ---------------------------------------------------------------------------
// K2a: sims[bt][h][half][k] = dot(q[bt,h,half,:], keys[h,k,half,:])
// ---------------------------------------------------------------------------
__global__ __launch_bounds__(128) void sim_kernel(const float* __restrict__ keys) {
    const int tile = blockIdx.x;   // 0..15
    const int h    = blockIdx.y;   // 0..3
    const int half = blockIdx.z;   // 0..1
    const int t    = threadIdx.x;

    __shared__ __align__(16) float ks[NKEY][DK];   // 32 KB
    __shared__ float sbuf[128][17];                // 8.5 KB (16-key chunks)

    const float4* kg = (const float4*)keys;
    #pragma unroll
    for (int i = 0; i < 16; i++) {
        int l = t + 128 * i;
        int k = l >> 4, c4 = l & 15;
        ((float4*)&ks[k][0])[c4] = kg[((size_t)(h * NKEY + k) * 2 + half) * 16 + c4];
    }

    const int token = tile * 128 + t;
    float4 qr[16];
    const float4* qg = (const float4*)(g_q + (size_t)token * QC + h * 128 + half * 64);
    #pragma unroll
    for (int i = 0; i < 16; i++) qr[i] = qg[i];
    __syncthreads();

    for (int kc = 0; kc < NKEY; kc += 16) {
        #pragma unroll
        for (int k = 0; k < 16; k++) {
            const float4* kr = (const float4*)&ks[kc + k][0];
            float p0 = 0.f, p1 = 0.f, p2 = 0.f, p3 = 0.f;
            #pragma unroll
            for (int i = 0; i < 16; i += 4) {
                float4 a, b;
                a = qr[i + 0]; b = kr[i + 0];
                p0 = fmaf(a.x, b.x, fmaf(a.y, b.y, fmaf(a.z, b.z, fmaf(a.w, b.w, p0))));
                a = qr[i + 1]; b = kr[i + 1];
                p1 = fmaf(a.x, b.x, fmaf(a.y, b.y, fmaf(a.z, b.z, fmaf(a.w, b.w, p1))));
                a = qr[i + 2]; b = kr[i + 2];
                p2 = fmaf(a.x, b.x, fmaf(a.y, b.y, fmaf(a.z, b.z, fmaf(a.w, b.w, p2))));
                a = qr[i + 3]; b = kr[i + 3];
                p3 = fmaf(a.x, b.x, fmaf(a.y, b.y, fmaf(a.z, b.z, fmaf(a.w, b.w, p3))));
            }
            sbuf[t][k] = __fadd_rn(__fadd_rn(p0, p1), __fadd_rn(p2, p3));
        }
        __syncthreads();
        #pragma unroll
        for (int i = 0; i < 16; i++) {
            int l = t + 128 * i;
            int tok = l >> 4, kk = l & 15;
            g_sims[((size_t)(tile * 128 + tok) * NH + h) * 256 + half * NKEY + kc + kk]
                = sbuf[tok][kk];
        }
        __syncthreads();
    }
}

// ---------------------------------------------------------------------------
// K2b: warp-level top-k. One warp per (bt,h).
// ---------------------------------------------------------------------------
__global__ __launch_bounds__(256) void topk_kernel() {
    const int w    = threadIdx.x >> 5;
    const int lane = threadIdx.x & 31;
    const int gw   = blockIdx.x * 8 + w;    // 0..8191 = bt*4 + h

    __shared__ __align__(16) float sv[8][256];
    __shared__ float s1s[8][8], s2s[8][8];
    __shared__ int   i1s[8][8], i2s[8][8];
    __shared__ float pv[8][64];
    __shared__ int   pix[8][64];

    const float4* sg = (const float4*)(g_sims + (size_t)gw * 256);
    ((float4*)sv[w])[lane]      = sg[lane];
    ((float4*)sv[w])[lane + 32] = sg[lane + 32];
    __syncwarp();

    #pragma unroll
    for (int hf = 0; hf < 2; hf++) {
        float* base = sv[w] + hf * 128;
        #pragma unroll
        for (int r = 0; r < 8; r++) {
            float v = base[lane];        int idx = lane;
            float v1 = base[lane + 32];  if (v1 > v) { v = v1; idx = lane + 32; }
            float v2 = base[lane + 64];  if (v2 > v) { v = v2; idx = lane + 64; }
            float v3 = base[lane + 96];  if (v3 > v) { v = v3; idx = lane + 96; }
            #pragma unroll
            for (int s = 16; s > 0; s >>= 1) {
                float ov = __shfl_xor_sync(0xffffffffu, v, s);
                int   oi = __shfl_xor_sync(0xffffffffu, idx, s);
                if (ov > v || (ov == v && oi < idx)) { v = ov; idx = oi; }
            }
            if (lane == 0) {
                if (hf == 0) { s1s[w][r] = v; i1s[w][r] = idx; }
                else         { s2s[w][r] = v; i2s[w][r] = idx; }
                base[idx] = -1e30f;
            }
            __syncwarp();
        }
    }

    #pragma unroll
    for (int pp = 0; pp < 2; pp++) {
        int p = lane + pp * 32;
        pv[w][p]  = __fadd_rn(s1s[w][p >> 3], s2s[w][p & 7]);
        pix[w][p] = i1s[w][p >> 3] * NKEY + i2s[w][p & 7];
    }
    __syncwarp();

    #pragma unroll
    for (int r = 0; r < 8; r++) {
        float v = pv[w][lane];        int idx = lane;
        float v1 = pv[w][lane + 32];  if (v1 > v) { v = v1; idx = lane + 32; }
        #pragma unroll
        for (int s = 16; s > 0; s >>= 1) {
            float ov = __shfl_xor_sync(0xffffffffu, v, s);
            int   oi = __shfl_xor_sync(0xffffffffu, idx, s);
            if (ov > v || (ov == v && oi < idx)) { v = ov; idx = oi; }
        }
        if (lane == 0) {
            g_scores [(size_t)gw * TOPK + r] = v;
            g_indices[(size_t)gw * TOPK + r] = pix[w][idx];
            pv[w][idx] = -1e30f;
        }
        __syncwarp();
    }
}

// ---------------------------------------------------------------------------
// K3a: gate — warp-per-(token, expert). Block = 8 warps; grid = (BT, 4 groups).
// Warp w of group eg handles expert e = eg*8 + w. No smem x (L1-shared row),
// no __syncthreads, one expert row per warp -> low regs, 4 blocks/SM.
// Inner dot is lane/chain-identical to the passing kernel: lane owns float4s
// lane + i*32, 4 chains by i%4, (a0+a1)+(a2+a3), shfl butterfly -> bit-identical.
// ---------------------------------------------------------------------------
__global__ __launch_bounds__(256) void gate_kernel(const float* __restrict__ x,
                                                   const float* __restrict__ e_down) {
    const int bt   = blockIdx.x;
    const int e    = blockIdx.y * 8 + (threadIdx.x >> 5);
    const int lane = threadIdx.x & 31;

    const int   idx = g_indices[(size_t)bt * 32 + e];
    const float sc  = fmaxf(g_scores[(size_t)bt * 32 + e], 0.f);

    const float4* xs4 = (const float4*)(x + (size_t)bt * DIM);
    const float4* row = (const float4*)(e_down + (size_t)idx * DIM);

    float a0 = 0.f, a1 = 0.f, a2 = 0.f, a3 = 0.f;
    #pragma unroll
    for (int i = 0; i < 16; i += 4) {
        float4 xa = xs4[lane + (i + 0) * 32], ra = row[lane + (i + 0) * 32];
        float4 xb = xs4[lane + (i + 1) * 32], rb = row[lane + (i + 1) * 32];
        float4 xc = xs4[lane + (i + 2) * 32], rc = row[lane + (i + 2) * 32];
        float4 xd = xs4[lane + (i + 3) * 32], rd = row[lane + (i + 3) * 32];
        a0 += xa.x * ra.x + xa.y * ra.y + xa.z * ra.z + xa.w * ra.w;
        a1 += xb.x * rb.x + xb.y * rb.y + xb.z * rb.z + xb.w * rb.w;
        a2 += xc.x * rc.x + xc.y * rc.y + xc.z * rc.z + xc.w * rc.w;
        a3 += xd.x * rd.x + xd.y * rd.y + xd.z * rd.z + xd.w * rd.w;
    }
    float acc = (a0 + a1) + (a2 + a3);
    #pragma unroll
    for (int s = 16; s > 0; s >>= 1) acc += __shfl_xor_sync(0xffffffffu, acc, s);
    if (lane == 0) {
        float sig = 1.f / (1.f + expf(-acc));
        g_gco[(size_t)bt * 32 + e] = acc * sig * sc;
    }
}

// ---------------------------------------------------------------------------
// K3b: out — out[bt][d] = sum_e gco[e] * e_up[idx_e][d].
// Grid = (token, D-chunk of 1024). Block 256; 1 float4 per thread.
// Accumulation order over e identical to Round-7 (bit-identical output).
// ---------------------------------------------------------------------------
__global__ __launch_bounds__(256) void out_kernel(const float* __restrict__ e_up,
                                                  float* __restrict__ out) {
    const int bt = blockIdx.x;
    const int c  = blockIdx.y;          // 0 or 1
    const int t  = threadIdx.x;

    __shared__ int   gix[32];
    __shared__ float gco[32];
    if (t < 32) {
        gix[t] = g_indices[(size_t)bt * 32 + t];
        gco[t] = g_gco[(size_t)bt * 32 + t];
    }
    __syncthreads();

    const int off = c * 256 + t;        // float4 index within the token row
    float4 o = make_float4(0.f, 0.f, 0.f, 0.f);
    #pragma unroll 8
    for (int e = 0; e < 32; e++) {
        const float gc = gco[e];
        float4 u = ((const float4*)(e_up + (size_t)gix[e] * DIM))[off];
        o.x += gc * u.x; o.y += gc * u.y; o.z += gc * u.z; o.w += gc * u.w;
    }
    ((float4*)(out + (size_t)bt * DIM))[off] = o;
}

// ---------------------------------------------------------------------------
extern "C" void kernel_launch(void* const* d_in, const int* in_sizes, int n_in,
                              void* d_out, int out_size) {
    const float* x      = (const float*)d_in[0];
    const float* Wq     = (const float*)d_in[1];
    const float* keys   = (const float*)d_in[2];
    const float* e_down = (const float*)d_in[3];
    const float* e_up   = (const float*)d_in[4];
    float* out = (float*)d_out;

    qproj_kernel<<<dim3(QC / 64, BT / 64), 256>>>(x, Wq);
    sim_kernel<<<dim3(BT / 128, NH, 2), 128>>>(keys);
    topk_kernel<<<BT * NH / 8, 256>>>();
    gate_kernel<<<dim3(BT, 4), 256>>>(x, e_down);
    out_kernel<<<dim3(BT, 2), 256>>>(e_up, out);
}

// round 11
// speedup vs baseline: 2.4227x; 1.0152x over previous
#include <cuda_runtime.h>
#include <math.h>
#include <stdint.h>

// Problem constants
#define BT   2048      // B*T
#define DIM  2048      // D
#define NH   4         // H
#define TOPK 8         // K
#define DK   64
#define NKEY 128       // NK
#define QC   512       // 2*H*DK

// Scratch (device globals — no allocation allowed)
__device__ float g_q[BT * QC];                 // 4 MB
__device__ float g_sims[BT * NH * 2 * NKEY];   // 8 MB
__device__ float g_scores[BT * NH * TOPK];
__device__ int   g_indices[BT * NH * TOPK];
__device__ float g_gco[BT * 32];               // gate coefficients

// ---- packed f32x2 helpers (sm_100+) --------------------------------------
#define FMA2(acc, a, b) asm("fma.rn.f32x2 %0, %1, %2, %0;" : "+l"(acc) : "l"(a), "l"(b))
#define ADD2(d, a, b)   asm("add.rn.f32x2 %0, %1, %2;" : "=l"(d) : "l"(a), "l"(b))
#define SUB2(d, a, b)   asm("sub.rn.f32x2 %0, %1, %2;" : "=l"(d) : "l"(a), "l"(b))
#define DUP2(d, s)      asm("mov.b64 %0, {%1, %1};"    : "=l"(d) : "f"(s))

// ---- cp.async helpers -----------------------------------------------------
__device__ __forceinline__ void cp16(uint32_t saddr, const void* gaddr) {
    asm volatile("cp.async.ca.shared.global [%0], [%1], 16;" :: "r"(saddr), "l"(gaddr));
}
#define CP_COMMIT() asm volatile("cp.async.commit_group;")
#define CP_WAIT(n)  asm volatile("cp.async.wait_group %0;" :: "n"(n))

// ---------------------------------------------------------------------------
// K1: q = x @ Wq  (M=2048, N=512, K=2048) fp32, 64x64 tile, 4x4/thread,
// packed f32x2 FFMA. cp.async double-buffered smem pipeline (no staging regs).
// A stored UNtransposed [m][k] (cp.async is copy-only); inner loop consumes
// 4 k-steps per float4 A-load so LDS count is unchanged. FMA2 chain order is
// bit-identical to the Round-7..10 kernel: ta = even kk ascending, tb = odd,
// same component/column mapping, same packed-rn Kahan combine per 32-k tile.
// ---------------------------------------------------------------------------
__global__ __launch_bounds__(256, 2) void qproj_kernel(const float* __restrict__ A,
                                                       const float* __restrict__ Bm) {
    __shared__ __align__(16) float As[2][64][36];   // [m][k], pad 36  (2×9216 B)
    __shared__ __align__(16) float Bs[2][32][68];   // [k][n], pad 68  (2×8704 B)

    const int t  = threadIdx.x;
    const int m0 = blockIdx.y * 64;
    const int n0 = blockIdx.x * 64;
    const int cx = t & 15;          // col group (4 cols)
    const int cy = t >> 4;          // row group (4 rows)

    // cp.async source/dest mapping: each thread copies 2 A-chunks + 2 B-chunks
    // A tile: 64 rows x 32 floats = 512 float4 ; idx -> row=idx>>3, c4=idx&7
    // B tile: 32 rows x 64 floats = 512 float4 ; idx -> kk =idx>>4, c4=idx&15
    const int a_r0 = t >> 3,        a_c0 = t & 7;
    const int a_r1 = (t + 256) >> 3, a_c1 = a_c0;    // (t+256)&7 == t&7
    const int b_k0 = t >> 4,        b_c0 = t & 15;
    const int b_k1 = (t + 256) >> 4, b_c1 = b_c0;    // (t+256)&15 == t&15

    const float* Ag0 = A  + (size_t)(m0 + a_r0) * DIM + a_c0 * 4;
    const float* Ag1 = A  + (size_t)(m0 + a_r1) * DIM + a_c1 * 4;
    const float* Bg0 = Bm + (size_t)b_k0 * QC + n0 + b_c0 * 4;
    const float* Bg1 = Bm + (size_t)b_k1 * QC + n0 + b_c1 * 4;

    uint32_t sA0[2], sA1[2], sB0[2], sB1[2];
    #pragma unroll
    for (int b = 0; b < 2; b++) {
        sA0[b] = (uint32_t)__cvta_generic_to_shared(&As[b][a_r0][a_c0 * 4]);
        sA1[b] = (uint32_t)__cvta_generic_to_shared(&As[b][a_r1][a_c1 * 4]);
        sB0[b] = (uint32_t)__cvta_generic_to_shared(&Bs[b][b_k0][b_c0 * 4]);
        sB1[b] = (uint32_t)__cvta_generic_to_shared(&Bs[b][b_k1][b_c1 * 4]);
    }

    unsigned long long acc[8], cmp[8];   // [i*2 + jp], each packs 2 cols
    #pragma unroll
    for (int e = 0; e < 8; e++) { acc[e] = 0ull; cmp[e] = 0ull; }

    // prologue: issue tile 0
    cp16(sA0[0], Ag0); cp16(sA1[0], Ag1);
    cp16(sB0[0], Bg0); cp16(sB1[0], Bg1);
    CP_COMMIT();

    #pragma unroll 1
    for (int kt = 0; kt < 64; kt++) {
        const int buf = kt & 1;
        const int k0n = (kt + 1) * 32;
        if (kt + 1 < 64) {
            const int nb = 1 - buf;
            cp16(sA0[nb], Ag0 + k0n);
            cp16(sA1[nb], Ag1 + k0n);
            cp16(sB0[nb], Bg0 + (size_t)k0n * QC);
            cp16(sB1[nb], Bg1 + (size_t)k0n * QC);
            CP_COMMIT();
            CP_WAIT(1);
        } else {
            CP_WAIT(0);
        }
        __syncthreads();

        unsigned long long ta[8], tb[8];
        #pragma unroll
        for (int e = 0; e < 8; e++) { ta[e] = 0ull; tb[e] = 0ull; }

        #pragma unroll
        for (int kkg = 0; kkg < 8; kkg++) {
            float4 am[4];
            ulonglong2 bq[4];
            #pragma unroll
            for (int i = 0; i < 4; i++)
                am[i] = *(const float4*)&As[buf][cy * 4 + i][kkg * 4];
            #pragma unroll
            for (int j = 0; j < 4; j++)
                bq[j] = *(const ulonglong2*)&Bs[buf][kkg * 4 + j][cx * 4];

            unsigned long long d;
            // kk = kkg*4+0 (even -> ta), component .x
            DUP2(d, am[0].x); FMA2(ta[0], d, bq[0].x); FMA2(ta[1], d, bq[0].y);
            DUP2(d, am[1].x); FMA2(ta[2], d, bq[0].x); FMA2(ta[3], d, bq[0].y);
            DUP2(d, am[2].x); FMA2(ta[4], d, bq[0].x); FMA2(ta[5], d, bq[0].y);
            DUP2(d, am[3].x); FMA2(ta[6], d, bq[0].x); FMA2(ta[7], d, bq[0].y);
            // kk+1 (odd -> tb), component .y
            DUP2(d, am[0].y); FMA2(tb[0], d, bq[1].x); FMA2(tb[1], d, bq[1].y);
            DUP2(d, am[1].y); FMA2(tb[2], d, bq[1].x); FMA2(tb[3], d, bq[1].y);
            DUP2(d, am[2].y); FMA2(tb[4], d, bq[1].x); FMA2(tb[5], d, bq[1].y);
            DUP2(d, am[3].y); FMA2(tb[6], d, bq[1].x); FMA2(tb[7], d, bq[1].y);
            // kk+2 (even -> ta), component .z
            DUP2(d, am[0].z); FMA2(ta[0], d, bq[2].x); FMA2(ta[1], d, bq[2].y);
            DUP2(d, am[1].z); FMA2(ta[2], d, bq[2].x); FMA2(ta[3], d, bq[2].y);
            DUP2(d, am[2].z); FMA2(ta[4], d, bq[2].x); FMA2(ta[5], d, bq[2].y);
            DUP2(d, am[3].z); FMA2(ta[6], d, bq[2].x); FMA2(ta[7], d, bq[2].y);
            // kk+3 (odd -> tb), component .w
            DUP2(d, am[0].w); FMA2(tb[0], d, bq[3].x); FMA2(tb[1], d, bq[3].y);
            DUP2(d, am[1].w); FMA2(tb[2], d, bq[3].x); FMA2(tb[3], d, bq[3].y);
            DUP2(d, am[2].w); FMA2(tb[4], d, bq[3].x); FMA2(tb[5], d, bq[3].y);
            DUP2(d, am[3].w); FMA2(tb[6], d, bq[3].x); FMA2(tb[7], d, bq[3].y);
        }

        // Kahan combine (packed, round-to-nearest, opaque to compiler)
        #pragma unroll
        for (int e = 0; e < 8; e++) {
            unsigned long long ts, y, t2, z;
            ADD2(ts, ta[e], tb[e]);
            SUB2(y, ts, cmp[e]);
            ADD2(t2, acc[e], y);
            SUB2(z, t2, acc[e]);
            SUB2(cmp[e], z, y);
            acc[e] = t2;
        }
        __syncthreads();
    }

    #pragma unroll
    for (int i = 0; i < 4; i++) {
        ulonglong2 o;
        o.x = acc[i * 2 + 0];
        o.y = acc[i * 2 + 1];
        *(ulonglong2*)(&g_q[(size_t)(m0 + cy * 4 + i) * QC + n0 + cx * 4]) = o;
    }
}

// ---------------------------------------------------------------------------
// K2a: sims[bt][h][half][k] = dot(q[bt,h,half,:], keys[h,k,half,:])
// ---------------------------------------------------------------------------
__global__ __launch_bounds__(128) void sim_kernel(const float* __restrict__ keys) {
    const int tile = blockIdx.x;   // 0..15
    const int h    = blockIdx.y;   // 0..3
    const int half = blockIdx.z;   // 0..1
    const int t    = threadIdx.x;

    __shared__ __align__(16) float ks[NKEY][DK];   // 32 KB
    __shared__ float sbuf[128][17];                // 8.5 KB (16-key chunks)

    const float4* kg = (const float4*)keys;
    #pragma unroll
    for (int i = 0; i < 16; i++) {
        int l = t + 128 * i;
        int k = l >> 4, c4 = l & 15;
        ((float4*)&ks[k][0])[c4] = kg[((size_t)(h * NKEY + k) * 2 + half) * 16 + c4];
    }

    const int token = tile * 128 + t;
    float4 qr[16];
    const float4* qg = (const float4*)(g_q + (size_t)token * QC + h * 128 + half * 64);
    #pragma unroll
    for (int i = 0; i < 16; i++) qr[i] = qg[i];
    __syncthreads();

    for (int kc = 0; kc < NKEY; kc += 16) {
        #pragma unroll
        for (int k = 0; k < 16; k++) {
            const float4* kr = (const float4*)&ks[kc + k][0];
            float p0 = 0.f, p1 = 0.f, p2 = 0.f, p3 = 0.f;
            #pragma unroll
            for (int i = 0; i < 16; i += 4) {
                float4 a, b;
                a = qr[i + 0]; b = kr[i + 0];
                p0 = fmaf(a.x, b.x, fmaf(a.y, b.y, fmaf(a.z, b.z, fmaf(a.w, b.w, p0))));
                a = qr[i + 1]; b = kr[i + 1];
                p1 = fmaf(a.x, b.x, fmaf(a.y, b.y, fmaf(a.z, b.z, fmaf(a.w, b.w, p1))));
                a = qr[i + 2]; b = kr[i + 2];
                p2 = fmaf(a.x, b.x, fmaf(a.y, b.y, fmaf(a.z, b.z, fmaf(a.w, b.w, p2))));
                a = qr[i + 3]; b = kr[i + 3];
                p3 = fmaf(a.x, b.x, fmaf(a.y, b.y, fmaf(a.z, b.z, fmaf(a.w, b.w, p3))));
            }
            sbuf[t][k] = __fadd_rn(__fadd_rn(p0, p1), __fadd_rn(p2, p3));
        }
        __syncthreads();
        #pragma unroll
        for (int i = 0; i < 16; i++) {
            int l = t + 128 * i;
            int tok = l >> 4, kk = l & 15;
            g_sims[((size_t)(tile * 128 + tok) * NH + h) * 256 + half * NKEY + kc + kk]
                = sbuf[tok][kk];
        }
        __syncthreads();
    }
}

// ---------------------------------------------------------------------------
// K2b: warp-level top-k. One warp per (bt,h).
// ---------------------------------------------------------------------------
__global__ __launch_bounds__(256) void topk_kernel() {
    const int w    = threadIdx.x >> 5;
    const int lane = threadIdx.x & 31;
    const int gw   = blockIdx.x * 8 + w;    // 0..8191 = bt*4 + h

    __shared__ __align__(16) float sv[8][256];
    __shared__ float s1s[8][8], s2s[8][8];
    __shared__ int   i1s[8][8], i2s[8][8];
    __shared__ float pv[8][64];
    __shared__ int   pix[8][64];

    const float4* sg = (const float4*)(g_sims + (size_t)gw * 256);
    ((float4*)sv[w])[lane]      = sg[lane];
    ((float4*)sv[w])[lane + 32] = sg[lane + 32];
    __syncwarp();

    #pragma unroll
    for (int hf = 0; hf < 2; hf++) {
        float* base = sv[w] + hf * 128;
        #pragma unroll
        for (int r = 0; r < 8; r++) {
            float v = base[lane];        int idx = lane;
            float v1 = base[lane + 32];  if (v1 > v) { v = v1; idx = lane + 32; }
            float v2 = base[lane + 64];  if (v2 > v) { v = v2; idx = lane + 64; }
            float v3 = base[lane + 96];  if (v3 > v) { v = v3; idx = lane + 96; }
            #pragma unroll
            for (int s = 16; s > 0; s >>= 1) {
                float ov = __shfl_xor_sync(0xffffffffu, v, s);
                int   oi = __shfl_xor_sync(0xffffffffu, idx, s);
                if (ov > v || (ov == v && oi < idx)) { v = ov; idx = oi; }
            }
            if (lane == 0) {
                if (hf == 0) { s1s[w][r] = v; i1s[w][r] = idx; }
                else         { s2s[w][r] = v; i2s[w][r] = idx; }
                base[idx] = -1e30f;
            }
            __syncwarp();
        }
    }

    #pragma unroll
    for (int pp = 0; pp < 2; pp++) {
        int p = lane + pp * 32;
        pv[w][p]  = __fadd_rn(s1s[w][p >> 3], s2s[w][p & 7]);
        pix[w][p] = i1s[w][p >> 3] * NKEY + i2s[w][p & 7];
    }
    __syncwarp();

    #pragma unroll
    for (int r = 0; r < 8; r++) {
        float v = pv[w][lane];        int idx = lane;
        float v1 = pv[w][lane + 32];  if (v1 > v) { v = v1; idx = lane + 32; }
        #pragma unroll
        for (int s = 16; s > 0; s >>= 1) {
            float ov = __shfl_xor_sync(0xffffffffu, v, s);
            int   oi = __shfl_xor_sync(0xffffffffu, idx, s);
            if (ov > v || (ov == v && oi < idx)) { v = ov; idx = oi; }
        }
        if (lane == 0) {
            g_scores [(size_t)gw * TOPK + r] = v;
            g_indices[(size_t)gw * TOPK + r] = pix[w][idx];
            pv[w][idx] = -1e30f;
        }
        __syncwarp();
    }
}

// ---------------------------------------------------------------------------
// K3a: gate — warp-per-(token, expert). Block = 8 warps; grid = (BT, 4 groups).
// ---------------------------------------------------------------------------
__global__ __launch_bounds__(256) void gate_kernel(const float* __restrict__ x,
                                                   const float* __restrict__ e_down) {
    const int bt   = blockIdx.x;
    const int e    = blockIdx.y * 8 + (threadIdx.x >> 5);
    const int lane = threadIdx.x & 31;

    const int   idx = g_indices[(size_t)bt * 32 + e];
    const float sc  = fmaxf(g_scores[(size_t)bt * 32 + e], 0.f);

    const float4* xs4 = (const float4*)(x + (size_t)bt * DIM);
    const float4* row = (const float4*)(e_down + (size_t)idx * DIM);

    float a0 = 0.f, a1 = 0.f, a2 = 0.f, a3 = 0.f;
    #pragma unroll
    for (int i = 0; i < 16; i += 4) {
        float4 xa = xs4[lane + (i + 0) * 32], ra = row[lane + (i + 0) * 32];
        float4 xb = xs4[lane + (i + 1) * 32], rb = row[lane + (i + 1) * 32];
        float4 xc = xs4[lane + (i + 2) * 32], rc = row[lane + (i + 2) * 32];
        float4 xd = xs4[lane + (i + 3) * 32], rd = row[lane + (i + 3) * 32];
        a0 += xa.x * ra.x + xa.y * ra.y + xa.z * ra.z + xa.w * ra.w;
        a1 += xb.x * rb.x + xb.y * rb.y + xb.z * rb.z + xb.w * rb.w;
        a2 += xc.x * rc.x + xc.y * rc.y + xc.z * rc.z + xc.w * rc.w;
        a3 += xd.x * rd.x + xd.y * rd.y + xd.z * rd.z + xd.w * rd.w;
    }
    float acc = (a0 + a1) + (a2 + a3);
    #pragma unroll
    for (int s = 16; s > 0; s >>= 1) acc += __shfl_xor_sync(0xffffffffu, acc, s);
    if (lane == 0) {
        float sig = 1.f / (1.f + expf(-acc));
        g_gco[(size_t)bt * 32 + e] = acc * sig * sc;
    }
}

// ---------------------------------------------------------------------------
// K3b: out — out[bt][d] = sum_e gco[e] * e_up[idx_e][d].
// ---------------------------------------------------------------------------
__global__ __launch_bounds__(256) void out_kernel(const float* __restrict__ e_up,
                                                  float* __restrict__ out) {
    const int bt = blockIdx.x;
    const int c  = blockIdx.y;          // 0 or 1
    const int t  = threadIdx.x;

    __shared__ int   gix[32];
    __shared__ float gco[32];
    if (t < 32) {
        gix[t] = g_indices[(size_t)bt * 32 + t];
        gco[t] = g_gco[(size_t)bt * 32 + t];
    }
    __syncthreads();

    const int off = c * 256 + t;        // float4 index within the token row
    float4 o = make_float4(0.f, 0.f, 0.f, 0.f);
    #pragma unroll 8
    for (int e = 0; e < 32; e++) {
        const float gc = gco[e];
        float4 u = ((const float4*)(e_up + (size_t)gix[e] * DIM))[off];
        o.x += gc * u.x; o.y += gc * u.y; o.z += gc * u.z; o.w += gc * u.w;
    }
    ((float4*)(out + (size_t)bt * DIM))[off] = o;
}

// ---------------------------------------------------------------------------
extern "C" void kernel_launch(void* const* d_in, const int* in_sizes, int n_in,
                              void* d_out, int out_size) {
    const float* x      = (const float*)d_in[0];
    const float* Wq     = (const float*)d_in[1];
    const float* keys   = (const float*)d_in[2];
    const float* e_down = (const float*)d_in[3];
    const float* e_up   = (const float*)d_in[4];
    float* out = (float*)d_out;

    qproj_kernel<<<dim3(QC / 64, BT / 64), 256>>>(x, Wq);
    sim_kernel<<<dim3(BT / 128, NH, 2), 128>>>(keys);
    topk_kernel<<<BT * NH / 8, 256>>>();
    gate_kernel<<<dim3(BT, 4), 256>>>(x, e_down);
    out_kernel<<<dim3(BT, 2), 256>>>(e_up, out);
}